// round 17
// baseline (speedup 1.0000x reference)
#include <cuda_runtime.h>

// TimeSeriesWineSNN: 3-layer LIF SNN, T=1000, B=4096, dims 8 -> 28 -> 8 -> 4.
// R17: 4-way warp specialization per quartet of warps:
//   A1: layer-1 neurons 4j+0,1   A2: layer-1 neurons 4j+2,3   (direct x loads)
//   B : layer 2 (+ spk2 store, ballots s2 word to smem)
//   C : layer 3 from ballot word (+ mem3/spk3 stores), one 4-step batch behind
// All arithmetic sequences byte-identical to the proven 4.4e-9 configuration
// (R16): rounded products, butterfly association, FFMA-folded L2 leaf,
// ballot+SEL L3, contracted membrane with exact -1.0 subtract.
// Barrier schedule: 251 instances of bar.sync(q,128);
//   A: {work k; bar} x250; bar   B: {bar; work k} x250; bar
//   C: bar; {bar; work k} x250   (rings: 8 slots, cadence 4 -> race-free)

constexpr int T_STEPS = 1000;
constexpr int BATCH   = 4096;
constexpr int NIN     = 8;
constexpr int NH1     = 28;
constexpr int NH2     = 8;
constexpr int NOUT    = 4;

constexpr int QPB = 2;                       // quartets (4 warps) per block
constexpr int BLOCK_THREADS = QPB * 128;     // 256
constexpr int BPB = QPB * 4;                 // batch elements per block
constexpr int NKB = T_STEPS / 4;             // 250 4-step batches

// lane-0 value of a shfl-down butterfly over 8 lanes (offsets 4,2,1)
__device__ __forceinline__ float butterfly8(const float* __restrict__ p) {
    float v0 = __fadd_rn(p[0], p[4]);
    float v1 = __fadd_rn(p[1], p[5]);
    float v2 = __fadd_rn(p[2], p[6]);
    float v3 = __fadd_rn(p[3], p[7]);
    v0 = __fadd_rn(v0, v2);
    v1 = __fadd_rn(v1, v3);
    return __fadd_rn(v0, v1);
}

// LIF (bit-exact): reset from previous m; contracted leak+integrate;
// exact -1.0 subtract; spike on new m.
__device__ __forceinline__ void lif(float& m, float cur, float& spk) {
    const float mo = m;
    float mn = __fmaf_rn(0.9f, mo, cur);
    if (mo > 1.0f) mn = __fsub_rn(mn, 1.0f);
    m = mn;
    spk = (mn > 1.0f) ? 1.0f : 0.0f;
}

__device__ __forceinline__ void bar_q(int barid) {
    asm volatile("bar.sync %0, 128;" :: "r"(barid) : "memory");
}

__global__ void __launch_bounds__(BLOCK_THREADS, 3)
snn_kernel(const float* __restrict__ x,
           const float* __restrict__ W1, const float* __restrict__ b1,
           const float* __restrict__ W2, const float* __restrict__ b2,
           const float* __restrict__ W3, const float* __restrict__ b3,
           float* __restrict__ out)
{
    const int warp = threadIdx.x >> 5;
    const int q    = warp >> 2;              // quartet within block
    const int role = warp & 3;               // 0,1 = A halves; 2 = B; 3 = C
    const int lane = threadIdx.x & 31;
    const int j    = lane & 7;               // lane within 8-thread group
    const int g    = lane >> 3;              // batch group within warp 0..3
    const int b    = blockIdx.x * BPB + q * 4 + g;
    const int grow = q * 4 + g;              // smem group row
    const int barid = q;

    __shared__ __align__(16) float s1buf[8][BPB][32];   // 8-slot s1 ring
    __shared__ unsigned s2w[8][QPB];                     // 8-slot s2 ballot ring

    constexpr size_t S1STRIDE = (size_t)BATCH * NH1;
    constexpr size_t S2STRIDE = (size_t)BATCH * NH2;
    constexpr size_t O3STRIDE = (size_t)BATCH * NOUT;

    if (role <= 1) {
        // ============ A half: 2 layer-1 neurons per lane ============
        const int rb = role * 2;             // neuron offset within lane quad
        float w1[2][8], bias1[2];
#pragma unroll
        for (int r = 0; r < 2; ++r) {
            const int n = 4 * j + rb + r;
            const bool v = (n < NH1);
            bias1[r] = v ? __ldg(&b1[n]) : 0.0f;
#pragma unroll
            for (int i = 0; i < 8; ++i)
                w1[r][i] = v ? __ldg(&W1[n * NIN + i]) : 0.0f;
        }
        float m1[2] = {0.f, 0.f};

        float* spk1p = out + 2ull * T_STEPS * BATCH * NOUT
                           + (size_t)b * NH1 + 4 * j + rb;

        const float4* __restrict__ xq =
            reinterpret_cast<const float4*>(x) + (size_t)b * 2;
        constexpr size_t XS4 = (size_t)BATCH * NIN / 4;  // float4 per timestep

        float4 pf[8];                         // next 4 steps of x (2 float4 each)
#pragma unroll
        for (int i = 0; i < 4; ++i) {
            pf[2 * i]     = xq[(size_t)i * XS4];
            pf[2 * i + 1] = xq[(size_t)i * XS4 + 1];
        }

        auto stepA = [&](float4 xa, float4 xb, int slot) {
            const float xs[8] = {xa.x, xa.y, xa.z, xa.w, xb.x, xb.y, xb.z, xb.w};
            float2 sp;
            float* spv = &sp.x;
#pragma unroll
            for (int r = 0; r < 2; ++r) {
                float p[8];
#pragma unroll
                for (int i = 0; i < 8; ++i)
                    p[i] = __fmul_rn(w1[r][i], xs[i]);
                float c = __fadd_rn(butterfly8(p), bias1[r]);
                lif(m1[r], c, spv[r]);
            }
            *reinterpret_cast<float2*>(&s1buf[slot][grow][4 * j + rb]) = sp;
            if (j < 7)
                *reinterpret_cast<float2*>(spk1p) = sp;
            spk1p += S1STRIDE;
        };

        for (int kb = 0; kb < NKB; ++kb) {
            const int s0 = (kb & 1) * 4;
            const bool more = (kb + 1 < NKB);
            const float4* pnx = xq + (size_t)(kb + 1) * 4 * XS4;
            stepA(pf[0], pf[1], s0 + 0);
            stepA(pf[2], pf[3], s0 + 1);
            if (more) { pf[0] = pnx[0]; pf[1] = pnx[1]; }
            stepA(pf[4], pf[5], s0 + 2);
            if (more) { pf[2] = pnx[XS4]; pf[3] = pnx[XS4 + 1]; }
            stepA(pf[6], pf[7], s0 + 3);
            if (more) {
                pf[4] = pnx[2 * XS4]; pf[5] = pnx[2 * XS4 + 1];
                pf[6] = pnx[3 * XS4]; pf[7] = pnx[3 * XS4 + 1];
            }
            bar_q(barid);                     // publish 4 slots (drains STS)
        }
        bar_q(barid);                         // final rendezvous (C drain)
    } else if (role == 2) {
        // ============ B: layer 2 + spk2 + s2 ballot word ============
        float w2[NH1];
#pragma unroll
        for (int k = 0; k < NH1; ++k) w2[k] = __ldg(&W2[j * NH1 + k]);
        const float bias2 = __ldg(&b2[j]);
        float m2 = 0.f;

        float* spk2p = out + 2ull * T_STEPS * BATCH * NOUT
                           + (size_t)T_STEPS * BATCH * NH1
                           + (size_t)b * NH2 + j;

        auto stepB = [&](int slot) {
            float s1v[28];
#pragma unroll
            for (int qd = 0; qd < 7; ++qd) {
                float4 s = *reinterpret_cast<const float4*>(&s1buf[slot][grow][4 * qd]);
                s1v[4 * qd + 0] = s.x; s1v[4 * qd + 1] = s.y;
                s1v[4 * qd + 2] = s.z; s1v[4 * qd + 3] = s.w;
            }
            // width-32 butterfly; LEAF FFMA-folded (products exact for 0/1 spikes)
            float q0[16];
#pragma unroll
            for (int i = 0; i < 12; ++i)
                q0[i] = __fmaf_rn(w2[i], s1v[i], __fmul_rn(w2[i + 16], s1v[i + 16]));
#pragma unroll
            for (int i = 12; i < 16; ++i)
                q0[i] = __fmul_rn(w2[i], s1v[i]);
            float r0[8];
#pragma unroll
            for (int i = 0; i < 8; ++i) r0[i] = __fadd_rn(q0[i], q0[i + 8]);
            float s4[4];
#pragma unroll
            for (int i = 0; i < 4; ++i) s4[i] = __fadd_rn(r0[i], r0[i + 4]);
            float t0 = __fadd_rn(s4[0], s4[2]);
            float t1 = __fadd_rn(s4[1], s4[3]);
            float a2 = __fadd_rn(__fadd_rn(t0, t1), bias2);

            const float mo2 = m2;
            float mn2 = __fmaf_rn(0.9f, mo2, a2);
            if (mo2 > 1.0f) mn2 = __fsub_rn(mn2, 1.0f);
            m2 = mn2;
            const bool sp2 = (mn2 > 1.0f);
            *spk2p = sp2 ? 1.0f : 0.0f;
            spk2p += S2STRIDE;

            const unsigned bal = __ballot_sync(0xffffffffu, sp2);
            if (lane == 0) s2w[slot][q] = bal;
        };

        for (int kb = 0; kb < NKB; ++kb) {
            bar_q(barid);                     // wait for A's 4 slots
            const int s0 = (kb & 1) * 4;
            stepB(s0 + 0);
            stepB(s0 + 1);
            stepB(s0 + 2);
            stepB(s0 + 3);
        }
        bar_q(barid);                         // final rendezvous
    } else {
        // ============ C: layer 3 from ballot word (1 batch behind B) ========
        const bool j4 = (j < 4);
        float w3[8];
#pragma unroll
        for (int i = 0; i < 8; ++i) w3[i] = j4 ? __ldg(&W3[j * NH2 + i]) : 0.0f;
        const float bias3 = j4 ? __ldg(&b3[j]) : 0.0f;
        float m3 = 0.f;

        float* mem3p = out                                  + (size_t)b * NOUT + j;
        float* spk3p = out + (size_t)T_STEPS * BATCH * NOUT + (size_t)b * NOUT + j;
        const int gsh = g << 3;

        auto stepC = [&](int slot) {
            const unsigned word = s2w[slot][q];
            const unsigned byte = word >> gsh;
            // product w3[i]*s2[i] == (bit ? w3[i] : 0); +/-0 diffs absorbed
            float p3[8];
#pragma unroll
            for (int i = 0; i < 8; ++i)
                p3[i] = (byte & (1u << i)) ? w3[i] : 0.0f;
            float a3 = __fadd_rn(butterfly8(p3), bias3);

            float s3;
            lif(m3, a3, s3);
            if (j4) {
                *mem3p = m3;
                *spk3p = s3;
            }
            mem3p += O3STRIDE;
            spk3p += O3STRIDE;
        };

        bar_q(barid);                         // skew: run one batch behind B
        for (int kb = 0; kb < NKB; ++kb) {
            bar_q(barid);                     // B's words for batch kb are ready
            const int s0 = (kb & 1) * 4;
            stepC(s0 + 0);
            stepC(s0 + 1);
            stepC(s0 + 2);
            stepC(s0 + 3);
        }
    }
}

extern "C" void kernel_launch(void* const* d_in, const int* in_sizes, int n_in,
                              void* d_out, int out_size) {
    const float* x  = (const float*)d_in[0];
    const float* W1 = (const float*)d_in[1];
    const float* b1 = (const float*)d_in[2];
    const float* W2 = (const float*)d_in[3];
    const float* b2 = (const float*)d_in[4];
    const float* W3 = (const float*)d_in[5];
    const float* b3 = (const float*)d_in[6];

    const int blocks = BATCH / BPB;          // 512
    snn_kernel<<<blocks, BLOCK_THREADS>>>(x, W1, b1, W2, b2, W3, b3, (float*)d_out);
}